// round 10
// baseline (speedup 1.0000x reference)
#include <cuda_runtime.h>
#include <cuda_fp16.h>
#include <cuda_bf16.h>
#include <cstdint>

#define BATCH 4
#define CIN   256
#define CH    128
#define NN    4096
#define ROW2  72                  /* padded smem row length in halfs (144 B) */
#define TB2   (128 * ROW2 * 2)    /* one 128x64 tile: 18432 bytes */
#define STG2  (2 * TB2)           /* one stage (A+B): 36864 bytes */
#define SMEM2 (2 * STG2)          /* 73728 bytes dynamic smem */
#define EROW  272                 /* epilogue staging row stride in bytes */
#define KSPLIT 2
#define THREADS 512               /* 16 warps, 4x4 warp grid, 32x32 per warp */

// ---------------- scratch (device globals; no allocs allowed) ----------------
__device__ __align__(16) __half        g_Wh[4][CIN * CH];            // fp16 weights: teta, gi, fi, out
__device__ __align__(16) __half        g_Xt[BATCH][NN * CIN];        // x^T: (NN, CIN) fp16
__device__ __align__(16) __half        g_T [BATCH][CH * NN];         // theta out flat == x1 (N,CH)
__device__ __align__(16) __half        g_G [BATCH][CH * NN];         // gi out flat == x3 (N,CH)
__device__ __align__(16) __half        g_Ft[BATCH][NN * CH];         // fi out as (NN, CH)
__device__ __align__(16) __nv_bfloat16 g_Gt[BATCH][CH * NN];         // x3^T * invZ: (CH, NN) bf16
__device__ __align__(16) __nv_bfloat16 g_E [BATCH][(size_t)NN * NN]; // exp(S) bf16
__device__ __align__(16) float         g_Z [BATCH][NN];              // column sums of exp(S)
__device__ __align__(16) float         g_Yp[KSPLIT][BATCH][NN * CH]; // split-K partials of Y
__device__ __align__(16) __half        g_Y [BATCH][NN * CH];         // summed Y (N,CH) fp16

// ====================== helpers (baseline PTX only) ==========================
__device__ __forceinline__ uint32_t smem_u32(const void* p) {
    uint32_t a;
    asm("{ .reg .u64 t; cvta.to.shared.u64 t, %1; cvt.u32.u64 %0, t; }" : "=r"(a) : "l"(p));
    return a;
}
__device__ __forceinline__ void cpa16(uint32_t s, const void* g) {
    asm volatile("cp.async.cg.shared.global [%0], [%1], 16;" :: "r"(s), "l"(g));
}
#define CPA_COMMIT() asm volatile("cp.async.commit_group;" ::: "memory")
#define CPA_WAIT0()  asm volatile("cp.async.wait_group 0;" ::: "memory")

__device__ __forceinline__ void ldsm4(uint32_t& r0, uint32_t& r1, uint32_t& r2, uint32_t& r3,
                                      uint32_t addr) {
    asm volatile("ldmatrix.sync.aligned.m8n8.x4.shared.b16 {%0,%1,%2,%3}, [%4];"
                 : "=r"(r0), "=r"(r1), "=r"(r2), "=r"(r3) : "r"(addr));
}
template <int KIND>   // 0 = fp16, 1 = bf16
__device__ __forceinline__ void mma16816(float (&d)[4], const uint32_t (&a)[4],
                                         uint32_t b0, uint32_t b1) {
    if (KIND == 0)
        asm volatile("mma.sync.aligned.m16n8k16.row.col.f32.f16.f16.f32 "
                     "{%0,%1,%2,%3}, {%4,%5,%6,%7}, {%8,%9}, {%0,%1,%2,%3};"
                     : "+f"(d[0]), "+f"(d[1]), "+f"(d[2]), "+f"(d[3])
                     : "r"(a[0]), "r"(a[1]), "r"(a[2]), "r"(a[3]), "r"(b0), "r"(b1));
    else
        asm volatile("mma.sync.aligned.m16n8k16.row.col.f32.bf16.bf16.f32 "
                     "{%0,%1,%2,%3}, {%4,%5,%6,%7}, {%8,%9}, {%0,%1,%2,%3};"
                     : "+f"(d[0]), "+f"(d[1]), "+f"(d[2]), "+f"(d[3])
                     : "r"(a[0]), "r"(a[1]), "r"(a[2]), "r"(a[3]), "r"(b0), "r"(b1));
}
// exp on the FMA pipe (no MUFU)
__device__ __forceinline__ float fast_exp(float x) {
    float y = x * 1.4426950408889634f;
    int ni = __float2int_rn(y);
    ni = max(ni, -120);
    float f = y - (float)ni;
    float p = 1.3333558146e-3f;
    p = fmaf(p, f, 9.6181291076e-3f);
    p = fmaf(p, f, 5.5504108665e-2f);
    p = fmaf(p, f, 2.4022650696e-1f);
    p = fmaf(p, f, 6.9314718056e-1f);
    p = fmaf(p, f, 1.0f);
    return __int_as_float(__float_as_int(p) + (ni << 23));
}
__device__ __forceinline__ uint32_t pack_h2(float a, float b) {
    __half2 h = __floats2half2_rn(a, b);
    return *reinterpret_cast<uint32_t*>(&h);
}

// async-stage a 128x64 16-bit tile (row stride 144 B in smem), 512 threads
__device__ __forceinline__ void stage64(uint32_t sbase, const uint16_t* src, int rstride,
                                        int row0, int k0, int tid) {
#pragma unroll
    for (int it = 0; it < 2; it++) {
        int u = it * THREADS + tid;
        int row = u >> 3, ch = u & 7;
        cpa16(sbase + (uint32_t)(row * (ROW2 * 2) + ch * 16),
              src + (size_t)(row0 + row) * rstride + k0 + ch * 8);
    }
}

// one 32-deep K slab, 32x32 warp tile: per ks, 4 ldsm bulk then 8 mma
template <int KIND>
__device__ __forceinline__ void slab(uint32_t aB, uint32_t bB, float (&acc)[2][4][4]) {
#pragma unroll
    for (int ks = 0; ks < 2; ks++) {
        uint32_t a[2][4], b[2][4];
#pragma unroll
        for (int mt = 0; mt < 2; mt++)
            ldsm4(a[mt][0], a[mt][1], a[mt][2], a[mt][3],
                  aB + mt * (16 * ROW2 * 2) + ks * 32);
#pragma unroll
        for (int np = 0; np < 2; np++)
            ldsm4(b[np][0], b[np][1], b[np][2], b[np][3],
                  bB + np * (16 * ROW2 * 2) + ks * 32);
#pragma unroll
        for (int np = 0; np < 2; np++)
#pragma unroll
            for (int mt = 0; mt < 2; mt++) {
                mma16816<KIND>(acc[mt][2 * np],     a[mt], b[np][0], b[np][1]);
                mma16816<KIND>(acc[mt][2 * np + 1], a[mt], b[np][2], b[np][3]);
            }
    }
}
__device__ __forceinline__ uint32_t a_off(int M0, int lane) {
    return (uint32_t)((M0 + (lane & 15)) * (ROW2 * 2) + (lane >> 4) * 16);
}
__device__ __forceinline__ uint32_t b_off(int N0, int lane) {
    int row = N0 + (lane & 7) + ((lane >> 4) & 1) * 8;
    return (uint32_t)(row * (ROW2 * 2) + ((lane >> 3) & 1) * 16);
}

// ============ 2-stage, 64-deep pipeline ======================================
#define PIPE2(C, KIND, STAGE_BODY)                                              \
    for (int cc = 0; cc < (C); cc++) {                                          \
        CPA_WAIT0();                                                            \
        __syncthreads();                                                        \
        { const int nx = cc + 1;                                                \
          if (nx < (C)) { const uint32_t sb = s0 + (uint32_t)(nx & 1) * STG2;   \
                          STAGE_BODY CPA_COMMIT(); } }                          \
        const uint32_t co = (uint32_t)(cc & 1) * STG2;                          \
        slab<KIND>(aB + co, bB + co, acc);                                      \
        slab<KIND>(aB + co + 64, bB + co + 64, acc);                            \
    }

// ---------------- tiny kernels ----------------------------------------------
__global__ void __launch_bounds__(256) k_cvtW(
    const float* __restrict__ tw, const float* __restrict__ gw,
    const float* __restrict__ fw, const float* __restrict__ ow)
{
    int i = blockIdx.x * 256 + threadIdx.x;           // 512 blocks
    int which = i >> 15, o = i & 32767;
    const float* src = which == 0 ? tw : (which == 1 ? gw : (which == 2 ? fw : ow));
    g_Wh[which][o] = __float2half(src[o]);
    if (i < BATCH * NN) (&g_Z[0][0])[i] = 0.0f;       // fused Z zeroing
}
__global__ void __launch_bounds__(256) k_sumY() {
    int i = blockIdx.x * 256 + threadIdx.x;
    const int b = i / (NN * CH / 4);
    const int o = (i % (NN * CH / 4)) * 4;
    float4 s0 = *(const float4*)(&g_Yp[0][b][o]);
    float4 s1 = *(const float4*)(&g_Yp[1][b][o]);
    *(uint2*)(&g_Y[b][o]) = make_uint2(pack_h2(s0.x + s1.x, s0.y + s1.y),
                                       pack_h2(s0.z + s1.z, s0.w + s1.w));
}

// ---------------- transposes -------------------------------------------------
__global__ void __launch_bounds__(256) k_transX(const float* __restrict__ x) {
    __shared__ float t[32][33];
    const int b = blockIdx.z;
    const float* src = x + (size_t)b * CIN * NN;
    __half* dst = g_Xt[b];
    const int c0 = blockIdx.x * 32, r0 = blockIdx.y * 32;
    const int tx = threadIdx.x, ty = threadIdx.y;
#pragma unroll
    for (int j = 0; j < 32; j += 8) t[ty + j][tx] = src[(size_t)(r0 + ty + j) * NN + c0 + tx];
    __syncthreads();
#pragma unroll
    for (int j = 0; j < 32; j += 8)
        dst[(size_t)(c0 + ty + j) * CIN + r0 + tx] = __float2half(t[tx][ty + j]);
}
__global__ void __launch_bounds__(256) k_transG() {    // also applies 1/Z
    __shared__ float t[32][33];
    const int b = blockIdx.z;
    const __half* src = g_G[b];
    const float* Zv  = g_Z[b];
    __nv_bfloat16* dst = g_Gt[b];
    const int c0 = blockIdx.x * 32;     // over CH
    const int r0 = blockIdx.y * 32;     // over NN
    const int tx = threadIdx.x, ty = threadIdx.y;
#pragma unroll
    for (int j = 0; j < 32; j += 8)
        t[ty + j][tx] = __fdividef(__half2float(src[(size_t)(r0 + ty + j) * CH + c0 + tx]),
                                   Zv[r0 + ty + j]);
    __syncthreads();
#pragma unroll
    for (int j = 0; j < 32; j += 8)
        dst[(size_t)(c0 + ty + j) * NN + r0 + tx] = __float2bfloat16(t[tx][ty + j]);
}

// ---------------- K1: theta/gi/fi convs --------------------------------------
__global__ void __launch_bounds__(THREADS, 2) k_qkv(
    const float* __restrict__ tb, const float* __restrict__ gb,
    const float* __restrict__ fb)
{
    extern __shared__ __align__(16) char dsm[];
    const uint32_t s0 = smem_u32(dsm);
    const int tid = threadIdx.x, lane = tid & 31, wid = tid >> 5;
    const int b = blockIdx.z, sec = blockIdx.y, j0 = blockIdx.x * 128;
    const uint16_t* Xt = (const uint16_t*)g_Xt[b];
    const uint16_t* Wh = (const uint16_t*)g_Wh[sec];  // 0=teta, 1=gi, 2=fi

    const int g = lane >> 2, tg = lane & 3;
    const int M0 = (wid & 3) * 32, N0 = (wid >> 2) * 32;
    const uint32_t aB = s0 + a_off(M0, lane);
    const uint32_t bB = s0 + TB2 + b_off(N0, lane);

    const uint16_t* Asrc = sec < 2 ? Wh : Xt;
    const uint16_t* Bsrc = sec < 2 ? Xt : Wh;
    const int arow0 = sec < 2 ? 0 : j0;
    const int brow0 = sec < 2 ? j0 : 0;

    float acc[2][4][4] = {};
    stage64(s0,       Asrc, CIN, arow0, 0, tid);
    stage64(s0 + TB2, Bsrc, CIN, brow0, 0, tid);
    CPA_COMMIT();
    PIPE2(CIN / 64, 0,
        stage64(sb,       Asrc, CIN, arow0, nx * 64, tid);
        stage64(sb + TB2, Bsrc, CIN, brow0, nx * 64, tid);
    )
    // ---- epilogue: stage fp16 tile in smem (stride EROW), coalesced copy-out
    __syncthreads();
    if (sec < 2) {
        const float* Bv = sec == 0 ? tb : gb;
#pragma unroll
        for (int mt = 0; mt < 2; mt++) {
            int rl = M0 + mt * 16 + g;
            float b0 = Bv[rl], b1 = Bv[rl + 8];
#pragma unroll
            for (int nt = 0; nt < 4; nt++) {
                int cl = N0 + nt * 8 + 2 * tg;
                *(uint32_t*)(dsm + rl * EROW + cl * 2)       = pack_h2(acc[mt][nt][0] + b0, acc[mt][nt][1] + b0);
                *(uint32_t*)(dsm + (rl + 8) * EROW + cl * 2) = pack_h2(acc[mt][nt][2] + b1, acc[mt][nt][3] + b1);
            }
        }
        __syncthreads();
        __half* Dst = sec == 0 ? g_T[b] : g_G[b];
#pragma unroll
        for (int it = 0; it < 4; it++) {
            int u = it * THREADS + tid;
            int row = u >> 4, ch = u & 15;
            uint4 v = *(const uint4*)(dsm + row * EROW + ch * 16);
            *(uint4*)(Dst + (size_t)row * NN + j0 + ch * 8) = v;
        }
    } else {                                           // fi: output (NN, CH)
#pragma unroll
        for (int mt = 0; mt < 2; mt++) {
            int rl = M0 + mt * 16 + g;
#pragma unroll
            for (int nt = 0; nt < 4; nt++) {
                int cl = N0 + nt * 8 + 2 * tg;
                float b0 = fb[cl], b1 = fb[cl + 1];
                *(uint32_t*)(dsm + rl * EROW + cl * 2)       = pack_h2(acc[mt][nt][0] + b0, acc[mt][nt][1] + b1);
                *(uint32_t*)(dsm + (rl + 8) * EROW + cl * 2) = pack_h2(acc[mt][nt][2] + b0, acc[mt][nt][3] + b1);
            }
        }
        __syncthreads();
        __half* Dst = g_Ft[b];
#pragma unroll
        for (int it = 0; it < 4; it++) {
            int u = it * THREADS + tid;
            int row = u >> 4, ch = u & 15;
            uint4 v = *(const uint4*)(dsm + row * EROW + ch * 16);
            *(uint4*)(Dst + (size_t)(j0 + row) * CH + ch * 8) = v;
        }
    }
}

// ---------------- K2: E = exp(x1 @ x2), fused col-sums, staged stores --------
__global__ void __launch_bounds__(THREADS, 2) k_scores() {
    extern __shared__ __align__(16) char dsm[];
    const uint32_t s0 = smem_u32(dsm);
    const int tid = threadIdx.x, lane = tid & 31, wid = tid >> 5;
    const int b = blockIdx.z, i0 = blockIdx.y * 128, j0 = blockIdx.x * 128;
    const uint16_t* A  = (const uint16_t*)g_T[b];    // (N,CH) flat
    const uint16_t* Bm = (const uint16_t*)g_Ft[b];   // (N,CH)
    __nv_bfloat16*  E  = g_E[b];

    const int g = lane >> 2, tg = lane & 3;
    const int M0 = (wid & 3) * 32, N0 = (wid >> 2) * 32;
    const uint32_t aB = s0 + a_off(M0, lane);
    const uint32_t bB = s0 + TB2 + b_off(N0, lane);

    float acc[2][4][4] = {};
    stage64(s0,       A,  CH, i0, 0, tid);
    stage64(s0 + TB2, Bm, CH, j0, 0, tid);
    CPA_COMMIT();
    PIPE2(CH / 64, 0,
        stage64(sb,       A,  CH, i0, nx * 64, tid);
        stage64(sb + TB2, Bm, CH, j0, nx * 64, tid);
    )
    // ---- epilogue: exp, colsums via shuffle, E staged through smem
    __syncthreads();
#pragma unroll
    for (int nt = 0; nt < 4; nt++) {
        float cs0 = 0.f, cs1 = 0.f;
        int cl = N0 + nt * 8 + 2 * tg;
#pragma unroll
        for (int mt = 0; mt < 2; mt++) {
            float e0 = fast_exp(acc[mt][nt][0]);
            float e1 = fast_exp(acc[mt][nt][1]);
            float e2 = fast_exp(acc[mt][nt][2]);
            float e3 = fast_exp(acc[mt][nt][3]);
            int rl = M0 + mt * 16 + g;
            *(__nv_bfloat162*)(dsm + rl * EROW + cl * 2)       = __floats2bfloat162_rn(e0, e1);
            *(__nv_bfloat162*)(dsm + (rl + 8) * EROW + cl * 2) = __floats2bfloat162_rn(e2, e3);
            cs0 += e0 + e2;
            cs1 += e1 + e3;
        }
        cs0 += __shfl_xor_sync(0xFFFFFFFFu, cs0, 4);
        cs0 += __shfl_xor_sync(0xFFFFFFFFu, cs0, 8);
        cs0 += __shfl_xor_sync(0xFFFFFFFFu, cs0, 16);
        cs1 += __shfl_xor_sync(0xFFFFFFFFu, cs1, 4);
        cs1 += __shfl_xor_sync(0xFFFFFFFFu, cs1, 8);
        cs1 += __shfl_xor_sync(0xFFFFFFFFu, cs1, 16);
        if (lane < 4) {
            atomicAdd(&g_Z[b][j0 + cl],     cs0);
            atomicAdd(&g_Z[b][j0 + cl + 1], cs1);
        }
    }
    __syncthreads();
#pragma unroll
    for (int it = 0; it < 4; it++) {
        int u = it * THREADS + tid;
        int row = u >> 4, ch = u & 15;
        uint4 v = *(const uint4*)(dsm + row * EROW + ch * 16);
        *(uint4*)(E + (size_t)(i0 + row) * NN + j0 + ch * 8) = v;
    }
}

// ---------------- K4: Yp[ks] = E-slice @ Gt^T, bf16 --------------------------
__global__ void __launch_bounds__(THREADS, 2) k_attnv() {
    extern __shared__ __align__(16) char dsm[];
    const uint32_t s0 = smem_u32(dsm);
    const int tid = threadIdx.x, lane = tid & 31, wid = tid >> 5;
    const int ks = blockIdx.x, i0 = blockIdx.y * 128, b = blockIdx.z;
    const int kbase = ks * (NN / KSPLIT);
    const uint16_t* E  = (const uint16_t*)g_E[b];
    const uint16_t* Gt = (const uint16_t*)g_Gt[b];
    float* Yp = g_Yp[ks][b];

    const int g = lane >> 2, tg = lane & 3;
    const int M0 = (wid & 3) * 32, N0 = (wid >> 2) * 32;
    const uint32_t aB = s0 + a_off(M0, lane);
    const uint32_t bB = s0 + TB2 + b_off(N0, lane);

    float acc[2][4][4] = {};
    stage64(s0,       E,  NN, i0, kbase, tid);
    stage64(s0 + TB2, Gt, NN, 0,  kbase, tid);
    CPA_COMMIT();
    PIPE2((NN / KSPLIT) / 64, 1,
        stage64(sb,       E,  NN, i0, kbase + nx * 64, tid);
        stage64(sb + TB2, Gt, NN, 0,  kbase + nx * 64, tid);
    )
#pragma unroll
    for (int mt = 0; mt < 2; mt++) {
        int r = i0 + M0 + mt * 16 + g;
#pragma unroll
        for (int nt = 0; nt < 4; nt++) {
            int c = N0 + nt * 8 + 2 * tg;
            *(float2*)(Yp + (size_t)r * CH + c)       = make_float2(acc[mt][nt][0], acc[mt][nt][1]);
            *(float2*)(Yp + (size_t)(r + 8) * CH + c) = make_float2(acc[mt][nt][2], acc[mt][nt][3]);
        }
    }
}

// ---------------- K5: out = x + out_w @ Y^T + out_b --------------------------
__global__ void __launch_bounds__(THREADS, 2) k_out(
    const float* __restrict__ x,
    const float* __restrict__ ob,
    float* __restrict__ out)
{
    extern __shared__ __align__(16) char dsm[];
    const uint32_t s0 = smem_u32(dsm);
    const int tid = threadIdx.x, lane = tid & 31, wid = tid >> 5;
    const int b = blockIdx.z, m0 = blockIdx.y * 128, n0 = blockIdx.x * 128;
    const uint16_t* Y  = (const uint16_t*)g_Y[b];
    const uint16_t* Wo = (const uint16_t*)g_Wh[3];

    const int g = lane >> 2, tg = lane & 3;
    const int M0 = (wid & 3) * 32, N0 = (wid >> 2) * 32;
    const uint32_t aB = s0 + a_off(M0, lane);
    const uint32_t bB = s0 + TB2 + b_off(N0, lane);

    float acc[2][4][4] = {};
    stage64(s0,       Wo, CH, m0, 0, tid);
    stage64(s0 + TB2, Y,  CH, n0, 0, tid);
    CPA_COMMIT();
    PIPE2(CH / 64, 0,
        stage64(sb,       Wo, CH, m0, nx * 64, tid);
        stage64(sb + TB2, Y,  CH, n0, nx * 64, tid);
    )
#pragma unroll
    for (int mt = 0; mt < 2; mt++) {
        int r = m0 + M0 + mt * 16 + g;
        float b0 = ob[r], b1 = ob[r + 8];
#pragma unroll
        for (int nt = 0; nt < 4; nt++) {
            int c = n0 + N0 + nt * 8 + 2 * tg;
            size_t o0 = ((size_t)b * CIN + r) * NN + c;
            size_t o1 = ((size_t)b * CIN + r + 8) * NN + c;
            float2 x0 = *(const float2*)(x + o0);
            float2 x1 = *(const float2*)(x + o1);
            *(float2*)(out + o0) = make_float2(acc[mt][nt][0] + b0 + x0.x, acc[mt][nt][1] + b0 + x0.y);
            *(float2*)(out + o1) = make_float2(acc[mt][nt][2] + b1 + x1.x, acc[mt][nt][3] + b1 + x1.y);
        }
    }
}

// -----------------------------------------------------------------------------
extern "C" void kernel_launch(void* const* d_in, const int* in_sizes, int n_in,
                              void* d_out, int out_size) {
    const float* x  = (const float*)d_in[0];
    const float* tw = (const float*)d_in[1];
    const float* tb = (const float*)d_in[2];
    const float* fw = (const float*)d_in[3];
    const float* fb = (const float*)d_in[4];
    const float* gw = (const float*)d_in[5];
    const float* gb = (const float*)d_in[6];
    const float* ow = (const float*)d_in[7];
    const float* ob = (const float*)d_in[8];
    float* out = (float*)d_out;

    static int attr_done = 0;
    if (!attr_done) {
        cudaFuncSetAttribute(k_qkv,    cudaFuncAttributeMaxDynamicSharedMemorySize, SMEM2);
        cudaFuncSetAttribute(k_scores, cudaFuncAttributeMaxDynamicSharedMemorySize, SMEM2);
        cudaFuncSetAttribute(k_attnv,  cudaFuncAttributeMaxDynamicSharedMemorySize, SMEM2);
        cudaFuncSetAttribute(k_out,    cudaFuncAttributeMaxDynamicSharedMemorySize, SMEM2);
        attr_done = 1;
    }

    k_cvtW<<<512, 256>>>(tw, gw, fw, ow);                       // weights->fp16 + Z zero
    k_transX<<<dim3(128, 8, BATCH), dim3(32, 8)>>>(x);
    k_qkv<<<dim3(32, 3, BATCH), THREADS, SMEM2>>>(tb, gb, fb);
    k_scores<<<dim3(32, 32, BATCH), THREADS, SMEM2>>>();
    k_transG<<<dim3(4, 128, BATCH), dim3(32, 8)>>>();           // includes 1/Z
    k_attnv<<<dim3(KSPLIT, 32, BATCH), THREADS, SMEM2>>>();
    k_sumY<<<2048, 256>>>();
    k_out<<<dim3(32, 2, BATCH), THREADS, SMEM2>>>(x, ob, out);
}

// round 11
// speedup vs baseline: 1.0539x; 1.0539x over previous
#include <cuda_runtime.h>
#include <cuda_fp16.h>
#include <cuda_bf16.h>
#include <cstdint>

#define BATCH 4
#define CIN   256
#define CH    128
#define NN    4096
#define ROW2  72                  /* padded smem row length in halfs (144 B) */
#define TB2   (128 * ROW2 * 2)    /* one 128x64 tile: 18432 bytes */
#define STG2  (2 * TB2)           /* one stage (A+B): 36864 bytes */
#define SMEM2 (2 * STG2)          /* 73728 bytes dynamic smem */
#define EROW  272                 /* epilogue staging row stride in bytes */
#define KSPLIT 2

// ---------------- scratch (device globals; no allocs allowed) ----------------
__device__ __align__(16) __half        g_Wh[4][CIN * CH];            // fp16 weights: teta, gi, fi, out
__device__ __align__(16) __half        g_Xt[BATCH][NN * CIN];        // x^T: (NN, CIN) fp16
__device__ __align__(16) __half        g_T [BATCH][CH * NN];         // theta out flat == x1 (N,CH)
__device__ __align__(16) __half        g_G [BATCH][CH * NN];         // gi out flat == x3 (N,CH)
__device__ __align__(16) __half        g_Ft[BATCH][NN * CH];         // fi out as (NN, CH)
__device__ __align__(16) __nv_bfloat16 g_Gt[BATCH][CH * NN];         // x3^T * invZ: (CH, NN) bf16
__device__ __align__(16) __nv_bfloat16 g_E [BATCH][(size_t)NN * NN]; // exp(S) bf16
__device__ __align__(16) float         g_Z [BATCH][NN];              // column sums of exp(S)
__device__ __align__(16) float         g_Yp[KSPLIT][BATCH][NN * CH]; // split-K partials of Y
__device__ __align__(16) __half        g_Y [BATCH][NN * CH];         // summed Y (N,CH) fp16

// ====================== helpers (baseline PTX only) ==========================
__device__ __forceinline__ uint32_t smem_u32(const void* p) {
    uint32_t a;
    asm("{ .reg .u64 t; cvta.to.shared.u64 t, %1; cvt.u32.u64 %0, t; }" : "=r"(a) : "l"(p));
    return a;
}
__device__ __forceinline__ void cpa16(uint32_t s, const void* g) {
    asm volatile("cp.async.cg.shared.global [%0], [%1], 16;" :: "r"(s), "l"(g));
}
#define CPA_COMMIT() asm volatile("cp.async.commit_group;" ::: "memory")
#define CPA_WAIT0()  asm volatile("cp.async.wait_group 0;" ::: "memory")

__device__ __forceinline__ void ldsm4(uint32_t& r0, uint32_t& r1, uint32_t& r2, uint32_t& r3,
                                      uint32_t addr) {
    asm volatile("ldmatrix.sync.aligned.m8n8.x4.shared.b16 {%0,%1,%2,%3}, [%4];"
                 : "=r"(r0), "=r"(r1), "=r"(r2), "=r"(r3) : "r"(addr));
}
template <int KIND>   // 0 = fp16, 1 = bf16
__device__ __forceinline__ void mma16816(float (&d)[4], const uint32_t (&a)[4],
                                         uint32_t b0, uint32_t b1) {
    if (KIND == 0)
        asm volatile("mma.sync.aligned.m16n8k16.row.col.f32.f16.f16.f32 "
                     "{%0,%1,%2,%3}, {%4,%5,%6,%7}, {%8,%9}, {%0,%1,%2,%3};"
                     : "+f"(d[0]), "+f"(d[1]), "+f"(d[2]), "+f"(d[3])
                     : "r"(a[0]), "r"(a[1]), "r"(a[2]), "r"(a[3]), "r"(b0), "r"(b1));
    else
        asm volatile("mma.sync.aligned.m16n8k16.row.col.f32.bf16.bf16.f32 "
                     "{%0,%1,%2,%3}, {%4,%5,%6,%7}, {%8,%9}, {%0,%1,%2,%3};"
                     : "+f"(d[0]), "+f"(d[1]), "+f"(d[2]), "+f"(d[3])
                     : "r"(a[0]), "r"(a[1]), "r"(a[2]), "r"(a[3]), "r"(b0), "r"(b1));
}
// exp via MUFU (ex2.approx) — 1 FMA-pipe mul + 1 MUFU op per element.
// Frees ~5 FMA issue slots/element vs the polynomial; MUFU overlaps tensor.
__device__ __forceinline__ float fast_exp(float x) {
    float y = x * 1.4426950408889634f;
    float r;
    asm("ex2.approx.f32 %0, %1;" : "=f"(r) : "f"(y));
    return r;
}
__device__ __forceinline__ uint32_t pack_h2(float a, float b) {
    __half2 h = __floats2half2_rn(a, b);
    return *reinterpret_cast<uint32_t*>(&h);
}

// async-stage a 128x64 16-bit tile (row stride 144 B in smem), 256 threads
__device__ __forceinline__ void stage64(uint32_t sbase, const uint16_t* src, int rstride,
                                        int row0, int k0, int tid) {
#pragma unroll
    for (int it = 0; it < 4; it++) {
        int u = it * 256 + tid;
        int row = u >> 3, ch = u & 7;
        cpa16(sbase + (uint32_t)(row * (ROW2 * 2) + ch * 16),
              src + (size_t)(row0 + row) * rstride + k0 + ch * 8);
    }
}

// ---- fragment bulk load (6 ldsm back-to-back) + dependency-free mma burst ---
__device__ __forceinline__ void ldfrags(uint32_t aB, uint32_t bB, int ks,
                                        uint32_t (&a)[2][4], uint32_t (&b)[4][4]) {
#pragma unroll
    for (int mt = 0; mt < 2; mt++)
        ldsm4(a[mt][0], a[mt][1], a[mt][2], a[mt][3],
              aB + mt * (16 * ROW2 * 2) + ks * 32);
#pragma unroll
    for (int np = 0; np < 4; np++)
        ldsm4(b[np][0], b[np][1], b[np][2], b[np][3],
              bB + np * (16 * ROW2 * 2) + ks * 32);
}
template <int KIND>
__device__ __forceinline__ void domma(const uint32_t (&a)[2][4], const uint32_t (&b)[4][4],
                                      float (&acc)[2][8][4]) {
#pragma unroll
    for (int np = 0; np < 4; np++)
#pragma unroll
        for (int mt = 0; mt < 2; mt++) {
            mma16816<KIND>(acc[mt][2 * np],     a[mt], b[np][0], b[np][1]);
            mma16816<KIND>(acc[mt][2 * np + 1], a[mt], b[np][2], b[np][3]);
        }
}
// one 32-deep K slab: 12 ldsm issued up-front, then 32 mma
template <int KIND>
__device__ __forceinline__ void slab(uint32_t aB, uint32_t bB, float (&acc)[2][8][4]) {
    uint32_t a0[2][4], b0[4][4], a1[2][4], b1[4][4];
    ldfrags(aB, bB, 0, a0, b0);
    ldfrags(aB, bB, 1, a1, b1);
    domma<KIND>(a0, b0, acc);
    domma<KIND>(a1, b1, acc);
}
__device__ __forceinline__ uint32_t a_off(int M0, int lane) {
    return (uint32_t)((M0 + (lane & 15)) * (ROW2 * 2) + (lane >> 4) * 16);
}
__device__ __forceinline__ uint32_t b_off(int N0, int lane) {
    int row = N0 + (lane & 7) + ((lane >> 4) & 1) * 8;
    return (uint32_t)(row * (ROW2 * 2) + ((lane >> 3) & 1) * 16);
}

// ============ 2-stage, 64-deep pipeline ======================================
#define PIPE2(C, KIND, STAGE_BODY)                                              \
    for (int cc = 0; cc < (C); cc++) {                                          \
        CPA_WAIT0();                                                            \
        __syncthreads();                                                        \
        { const int nx = cc + 1;                                                \
          if (nx < (C)) { const uint32_t sb = s0 + (uint32_t)(nx & 1) * STG2;   \
                          STAGE_BODY CPA_COMMIT(); } }                          \
        const uint32_t co = (uint32_t)(cc & 1) * STG2;                          \
        slab<KIND>(aB + co, bB + co, acc);                                      \
        slab<KIND>(aB + co + 64, bB + co + 64, acc);                            \
    }

// ---------------- tiny kernels ----------------------------------------------
__global__ void __launch_bounds__(256) k_cvtW(
    const float* __restrict__ tw, const float* __restrict__ gw,
    const float* __restrict__ fw, const float* __restrict__ ow)
{
    int i = blockIdx.x * 256 + threadIdx.x;           // 512 blocks
    int which = i >> 15, o = i & 32767;
    const float* src = which == 0 ? tw : (which == 1 ? gw : (which == 2 ? fw : ow));
    g_Wh[which][o] = __float2half(src[o]);
    if (i < BATCH * NN) (&g_Z[0][0])[i] = 0.0f;       // fused Z zeroing
}
__global__ void __launch_bounds__(256) k_sumY() {
    int i = blockIdx.x * 256 + threadIdx.x;
    const int b = i / (NN * CH / 4);
    const int o = (i % (NN * CH / 4)) * 4;
    float4 s0 = *(const float4*)(&g_Yp[0][b][o]);
    float4 s1 = *(const float4*)(&g_Yp[1][b][o]);
    *(uint2*)(&g_Y[b][o]) = make_uint2(pack_h2(s0.x + s1.x, s0.y + s1.y),
                                       pack_h2(s0.z + s1.z, s0.w + s1.w));
}

// ---------------- transposes -------------------------------------------------
__global__ void __launch_bounds__(256) k_transX(const float* __restrict__ x) {
    __shared__ float t[32][33];
    const int b = blockIdx.z;
    const float* src = x + (size_t)b * CIN * NN;
    __half* dst = g_Xt[b];
    const int c0 = blockIdx.x * 32, r0 = blockIdx.y * 32;
    const int tx = threadIdx.x, ty = threadIdx.y;
#pragma unroll
    for (int j = 0; j < 32; j += 8) t[ty + j][tx] = src[(size_t)(r0 + ty + j) * NN + c0 + tx];
    __syncthreads();
#pragma unroll
    for (int j = 0; j < 32; j += 8)
        dst[(size_t)(c0 + ty + j) * CIN + r0 + tx] = __float2half(t[tx][ty + j]);
}
__global__ void __launch_bounds__(256) k_transG() {    // also applies 1/Z
    __shared__ float t[32][33];
    const int b = blockIdx.z;
    const __half* src = g_G[b];
    const float* Zv  = g_Z[b];
    __nv_bfloat16* dst = g_Gt[b];
    const int c0 = blockIdx.x * 32;     // over CH
    const int r0 = blockIdx.y * 32;     // over NN
    const int tx = threadIdx.x, ty = threadIdx.y;
#pragma unroll
    for (int j = 0; j < 32; j += 8)
        t[ty + j][tx] = __fdividef(__half2float(src[(size_t)(r0 + ty + j) * CH + c0 + tx]),
                                   Zv[r0 + ty + j]);
    __syncthreads();
#pragma unroll
    for (int j = 0; j < 32; j += 8)
        dst[(size_t)(c0 + ty + j) * NN + r0 + tx] = __float2bfloat16(t[tx][ty + j]);
}

// ---------------- K1: theta/gi/fi convs --------------------------------------
__global__ void __launch_bounds__(256, 2) k_qkv(
    const float* __restrict__ tb, const float* __restrict__ gb,
    const float* __restrict__ fb)
{
    extern __shared__ __align__(16) char dsm[];
    const uint32_t s0 = smem_u32(dsm);
    const int tid = threadIdx.x, lane = tid & 31, wid = tid >> 5;
    const int b = blockIdx.z, sec = blockIdx.y, j0 = blockIdx.x * 128;
    const uint16_t* Xt = (const uint16_t*)g_Xt[b];
    const uint16_t* Wh = (const uint16_t*)g_Wh[sec];  // 0=teta, 1=gi, 2=fi

    const int g = lane >> 2, tg = lane & 3;
    const int M0 = (wid & 3) * 32, N0 = (wid >> 2) * 64;
    const uint32_t aB = s0 + a_off(M0, lane);
    const uint32_t bB = s0 + TB2 + b_off(N0, lane);

    const uint16_t* Asrc = sec < 2 ? Wh : Xt;
    const uint16_t* Bsrc = sec < 2 ? Xt : Wh;
    const int arow0 = sec < 2 ? 0 : j0;
    const int brow0 = sec < 2 ? j0 : 0;

    float acc[2][8][4] = {};
    stage64(s0,       Asrc, CIN, arow0, 0, tid);
    stage64(s0 + TB2, Bsrc, CIN, brow0, 0, tid);
    CPA_COMMIT();
    PIPE2(CIN / 64, 0,
        stage64(sb,       Asrc, CIN, arow0, nx * 64, tid);
        stage64(sb + TB2, Bsrc, CIN, brow0, nx * 64, tid);
    )
    // ---- epilogue: stage fp16 tile in smem (stride EROW), coalesced copy-out
    __syncthreads();
    if (sec < 2) {
        const float* Bv = sec == 0 ? tb : gb;
#pragma unroll
        for (int mt = 0; mt < 2; mt++) {
            int rl = M0 + mt * 16 + g;
            float b0 = Bv[rl], b1 = Bv[rl + 8];
#pragma unroll
            for (int nt = 0; nt < 8; nt++) {
                int cl = N0 + nt * 8 + 2 * tg;
                *(uint32_t*)(dsm + rl * EROW + cl * 2)       = pack_h2(acc[mt][nt][0] + b0, acc[mt][nt][1] + b0);
                *(uint32_t*)(dsm + (rl + 8) * EROW + cl * 2) = pack_h2(acc[mt][nt][2] + b1, acc[mt][nt][3] + b1);
            }
        }
        __syncthreads();
        __half* Dst = sec == 0 ? g_T[b] : g_G[b];
#pragma unroll
        for (int it = 0; it < 8; it++) {
            int u = it * 256 + tid;
            int row = u >> 4, ch = u & 15;
            uint4 v = *(const uint4*)(dsm + row * EROW + ch * 16);
            *(uint4*)(Dst + (size_t)row * NN + j0 + ch * 8) = v;
        }
    } else {                                           // fi: output (NN, CH)
#pragma unroll
        for (int mt = 0; mt < 2; mt++) {
            int rl = M0 + mt * 16 + g;
#pragma unroll
            for (int nt = 0; nt < 8; nt++) {
                int cl = N0 + nt * 8 + 2 * tg;
                float b0 = fb[cl], b1 = fb[cl + 1];
                *(uint32_t*)(dsm + rl * EROW + cl * 2)       = pack_h2(acc[mt][nt][0] + b0, acc[mt][nt][1] + b1);
                *(uint32_t*)(dsm + (rl + 8) * EROW + cl * 2) = pack_h2(acc[mt][nt][2] + b0, acc[mt][nt][3] + b1);
            }
        }
        __syncthreads();
        __half* Dst = g_Ft[b];
#pragma unroll
        for (int it = 0; it < 8; it++) {
            int u = it * 256 + tid;
            int row = u >> 4, ch = u & 15;
            uint4 v = *(const uint4*)(dsm + row * EROW + ch * 16);
            *(uint4*)(Dst + (size_t)(j0 + row) * CH + ch * 8) = v;
        }
    }
}

// ---------------- K2: E = exp(x1 @ x2), fused col-sums, staged stores --------
__global__ void __launch_bounds__(256, 2) k_scores() {
    extern __shared__ __align__(16) char dsm[];
    const uint32_t s0 = smem_u32(dsm);
    const int tid = threadIdx.x, lane = tid & 31, wid = tid >> 5;
    const int b = blockIdx.z, i0 = blockIdx.y * 128, j0 = blockIdx.x * 128;
    const uint16_t* A  = (const uint16_t*)g_T[b];    // (N,CH) flat
    const uint16_t* Bm = (const uint16_t*)g_Ft[b];   // (N,CH)
    __nv_bfloat16*  E  = g_E[b];

    const int g = lane >> 2, tg = lane & 3;
    const int M0 = (wid & 3) * 32, N0 = (wid >> 2) * 64;
    const uint32_t aB = s0 + a_off(M0, lane);
    const uint32_t bB = s0 + TB2 + b_off(N0, lane);

    float acc[2][8][4] = {};
    stage64(s0,       A,  CH, i0, 0, tid);
    stage64(s0 + TB2, Bm, CH, j0, 0, tid);
    CPA_COMMIT();
    PIPE2(CH / 64, 0,
        stage64(sb,       A,  CH, i0, nx * 64, tid);
        stage64(sb + TB2, Bm, CH, j0, nx * 64, tid);
    )
    // ---- epilogue: exp (MUFU), colsums via shuffle, E staged through smem
    __syncthreads();
#pragma unroll
    for (int nt = 0; nt < 8; nt++) {
        float cs0 = 0.f, cs1 = 0.f;
        int cl = N0 + nt * 8 + 2 * tg;
#pragma unroll
        for (int mt = 0; mt < 2; mt++) {
            float e0 = fast_exp(acc[mt][nt][0]);
            float e1 = fast_exp(acc[mt][nt][1]);
            float e2 = fast_exp(acc[mt][nt][2]);
            float e3 = fast_exp(acc[mt][nt][3]);
            int rl = M0 + mt * 16 + g;
            *(__nv_bfloat162*)(dsm + rl * EROW + cl * 2)       = __floats2bfloat162_rn(e0, e1);
            *(__nv_bfloat162*)(dsm + (rl + 8) * EROW + cl * 2) = __floats2bfloat162_rn(e2, e3);
            cs0 += e0 + e2;
            cs1 += e1 + e3;
        }
        cs0 += __shfl_xor_sync(0xFFFFFFFFu, cs0, 4);
        cs0 += __shfl_xor_sync(0xFFFFFFFFu, cs0, 8);
        cs0 += __shfl_xor_sync(0xFFFFFFFFu, cs0, 16);
        cs1 += __shfl_xor_sync(0xFFFFFFFFu, cs1, 4);
        cs1 += __shfl_xor_sync(0xFFFFFFFFu, cs1, 8);
        cs1 += __shfl_xor_sync(0xFFFFFFFFu, cs1, 16);
        if (lane < 4) {
            atomicAdd(&g_Z[b][j0 + cl],     cs0);
            atomicAdd(&g_Z[b][j0 + cl + 1], cs1);
        }
    }
    __syncthreads();
#pragma unroll
    for (int it = 0; it < 8; it++) {
        int u = it * 256 + tid;
        int row = u >> 4, ch = u & 15;
        uint4 v = *(const uint4*)(dsm + row * EROW + ch * 16);
        *(uint4*)(E + (size_t)(i0 + row) * NN + j0 + ch * 8) = v;
    }
}

// ---------------- K4: Yp[ks] = E-slice @ Gt^T, bf16 --------------------------
__global__ void __launch_bounds__(256, 2) k_attnv() {
    extern __shared__ __align__(16) char dsm[];
    const uint32_t s0 = smem_u32(dsm);
    const int tid = threadIdx.x, lane = tid & 31, wid = tid >> 5;
    const int ks = blockIdx.x, i0 = blockIdx.y * 128, b = blockIdx.z;
    const int kbase = ks * (NN / KSPLIT);
    const uint16_t* E  = (const uint16_t*)g_E[b];
    const uint16_t* Gt = (const uint16_t*)g_Gt[b];
    float* Yp = g_Yp[ks][b];

    const int g = lane >> 2, tg = lane & 3;
    const int M0 = (wid & 3) * 32, N0 = (wid >> 2) * 64;
    const uint32_t aB = s0 + a_off(M0, lane);
    const uint32_t bB = s0 + TB2 + b_off(N0, lane);

    float acc[2][8][4] = {};
    stage64(s0,       E,  NN, i0, kbase, tid);
    stage64(s0 + TB2, Gt, NN, 0,  kbase, tid);
    CPA_COMMIT();
    PIPE2((NN / KSPLIT) / 64, 1,
        stage64(sb,       E,  NN, i0, kbase + nx * 64, tid);
        stage64(sb + TB2, Gt, NN, 0,  kbase + nx * 64, tid);
    )
#pragma unroll
    for (int mt = 0; mt < 2; mt++) {
        int r = i0 + M0 + mt * 16 + g;
#pragma unroll
        for (int nt = 0; nt < 8; nt++) {
            int c = N0 + nt * 8 + 2 * tg;
            *(float2*)(Yp + (size_t)r * CH + c)       = make_float2(acc[mt][nt][0], acc[mt][nt][1]);
            *(float2*)(Yp + (size_t)(r + 8) * CH + c) = make_float2(acc[mt][nt][2], acc[mt][nt][3]);
        }
    }
}

// ---------------- K5: out = x + out_w @ Y^T + out_b --------------------------
__global__ void __launch_bounds__(256, 2) k_out(
    const float* __restrict__ x,
    const float* __restrict__ ob,
    float* __restrict__ out)
{
    extern __shared__ __align__(16) char dsm[];
    const uint32_t s0 = smem_u32(dsm);
    const int tid = threadIdx.x, lane = tid & 31, wid = tid >> 5;
    const int b = blockIdx.z, m0 = blockIdx.y * 128, n0 = blockIdx.x * 128;
    const uint16_t* Y  = (const uint16_t*)g_Y[b];
    const uint16_t* Wo = (const uint16_t*)g_Wh[3];

    const int g = lane >> 2, tg = lane & 3;
    const int M0 = (wid & 3) * 32, N0 = (wid >> 2) * 64;
    const uint32_t aB = s0 + a_off(M0, lane);
    const uint32_t bB = s0 + TB2 + b_off(N0, lane);

    float acc[2][8][4] = {};
    stage64(s0,       Wo, CH, m0, 0, tid);
    stage64(s0 + TB2, Y,  CH, n0, 0, tid);
    CPA_COMMIT();
    PIPE2(CH / 64, 0,
        stage64(sb,       Wo, CH, m0, nx * 64, tid);
        stage64(sb + TB2, Y,  CH, n0, nx * 64, tid);
    )
#pragma unroll
    for (int mt = 0; mt < 2; mt++) {
        int r = m0 + M0 + mt * 16 + g;
        float b0 = ob[r], b1 = ob[r + 8];
#pragma unroll
        for (int nt = 0; nt < 8; nt++) {
            int c = n0 + N0 + nt * 8 + 2 * tg;
            size_t o0 = ((size_t)b * CIN + r) * NN + c;
            size_t o1 = ((size_t)b * CIN + r + 8) * NN + c;
            float2 x0 = *(const float2*)(x + o0);
            float2 x1 = *(const float2*)(x + o1);
            *(float2*)(out + o0) = make_float2(acc[mt][nt][0] + b0 + x0.x, acc[mt][nt][1] + b0 + x0.y);
            *(float2*)(out + o1) = make_float2(acc[mt][nt][2] + b1 + x1.x, acc[mt][nt][3] + b1 + x1.y);
        }
    }
}

// -----------------------------------------------------------------------------
extern "C" void kernel_launch(void* const* d_in, const int* in_sizes, int n_in,
                              void* d_out, int out_size) {
    const float* x  = (const float*)d_in[0];
    const float* tw = (const float*)d_in[1];
    const float* tb = (const float*)d_in[2];
    const float* fw = (const float*)d_in[3];
    const float* fb = (const float*)d_in[4];
    const float* gw = (const float*)d_in[5];
    const float* gb = (const float*)d_in[6];
    const float* ow = (const float*)d_in[7];
    const float* ob = (const float*)d_in[8];
    float* out = (float*)d_out;

    static int attr_done = 0;
    if (!attr_done) {
        cudaFuncSetAttribute(k_qkv,    cudaFuncAttributeMaxDynamicSharedMemorySize, SMEM2);
        cudaFuncSetAttribute(k_scores, cudaFuncAttributeMaxDynamicSharedMemorySize, SMEM2);
        cudaFuncSetAttribute(k_attnv,  cudaFuncAttributeMaxDynamicSharedMemorySize, SMEM2);
        cudaFuncSetAttribute(k_out,    cudaFuncAttributeMaxDynamicSharedMemorySize, SMEM2);
        attr_done = 1;
    }

    k_cvtW<<<512, 256>>>(tw, gw, fw, ow);                       // weights->fp16 + Z zero
    k_transX<<<dim3(128, 8, BATCH), dim3(32, 8)>>>(x);
    k_qkv<<<dim3(32, 3, BATCH), 256, SMEM2>>>(tb, gb, fb);
    k_scores<<<dim3(32, 32, BATCH), 256, SMEM2>>>();
    k_transG<<<dim3(4, 128, BATCH), dim3(32, 8)>>>();           // includes 1/Z
    k_attnv<<<dim3(KSPLIT, 32, BATCH), 256, SMEM2>>>();
    k_sumY<<<2048, 256>>>();
    k_out<<<dim3(32, 2, BATCH), 256, SMEM2>>>(x, ob, out);
}